// round 11
// baseline (speedup 1.0000x reference)
#include <cuda_runtime.h>

#define BQ 2
#define NPTS 512
#define INDIM 512
#define MEMD 300
#define HIDD 64
#define NEG 0.01f
#define NN (NPTS*NPTS)

typedef unsigned long long ull;

// ---------------- scratch ----------------
__device__ float g_h[1024*MEMD];
__device__ float g_s[1024*128];
__device__ float g_u[BQ*NN];
__device__ float g_f[1024*MEMD];
__device__ float g_sum[4];     // [layer][batch]

// ---------------- f32x2 helpers ----------------
__device__ __forceinline__ ull dup2(float x) {
    ull r; asm("mov.b64 %0, {%1,%1};" : "=l"(r) : "f"(x)); return r;
}
__device__ __forceinline__ void ffma2(ull& d, ull a, ull b) {
    asm("fma.rn.f32x2 %0, %1, %2, %0;" : "+l"(d) : "l"(a), "l"(b));
}
__device__ __forceinline__ float2 unpk(ull v) {
    float2 r; asm("mov.b64 {%0,%1}, %2;" : "=f"(r.x), "=f"(r.y) : "l"(v)); return r;
}

// ====== GEMM core: 32x64 tile, 128 thr, 4x4 micro, f32x2, reg-staged prefetch ======
// C[cr0..+32, cc0..+64] = scale * A[ar0..+32, :K] @ B[:K, bc0..+64] + bias
// Inner step: 1 LDS128(A) + 1 LDS128(B) + 4 dup + 8 FFMA2  = 14 instr / 16 MAC
__device__ __forceinline__ void gemm32(
    const float* __restrict__ A, int lda, int ar0, int K,
    const float* __restrict__ B, int ldb, int bc0, int bcmax,
    float* __restrict__ C, int ldc, int cr0, int cc0, int ccmax,
    const float* __restrict__ bias, float scale)
{
    __shared__ __align__(16) float As[16*36];   // [k][row], stride 36
    __shared__ __align__(16) float Bs[16*68];   // [k][col], stride 68
    int tid = threadIdx.x;
    int tx = tid & 15, ty = tid >> 4;           // tx: col-quad(16), ty: row-quad(8)
    int ty4 = ty*4, tx4 = tx*4;
    int kA = tid & 15, rA = tid >> 4;           // A stage: 4 elems/thread (rows rA+8p)
    int cB = tid & 63, kB = tid >> 6;           // B stage: 8 elems/thread
    int bc = bc0 + cB;
    bool bok = bc < bcmax;
    ull acc[4][2] = {};                         // [row][colpair]
    float ra[4], rb[8];
    // prefetch chunk 0
    #pragma unroll
    for (int p = 0; p < 4; p++)
        ra[p] = (kA < K) ? A[(size_t)(ar0 + rA + 8*p)*lda + kA] : 0.f;
    #pragma unroll
    for (int p = 0; p < 8; p++) {
        int bk = kB + 2*p;
        rb[p] = (bk < K && bok) ? B[(size_t)bk*ldb + bc] : 0.f;
    }
    for (int k0 = 0; k0 < K; k0 += 16) {
        #pragma unroll
        for (int p = 0; p < 4; p++) As[kA*36 + rA + 8*p] = ra[p];
        #pragma unroll
        for (int p = 0; p < 8; p++) Bs[(kB + 2*p)*68 + cB] = rb[p];
        __syncthreads();
        int kn = k0 + 16;
        if (kn < K) {                            // prefetch next chunk during compute
            #pragma unroll
            for (int p = 0; p < 4; p++) {
                int ac = kn + kA;
                ra[p] = (ac < K) ? A[(size_t)(ar0 + rA + 8*p)*lda + ac] : 0.f;
            }
            #pragma unroll
            for (int p = 0; p < 8; p++) {
                int bk = kn + kB + 2*p;
                rb[p] = (bk < K && bok) ? B[(size_t)bk*ldb + bc] : 0.f;
            }
        }
        #pragma unroll
        for (int k = 0; k < 16; k++) {
            float4 av = *(const float4*)&As[k*36 + ty4];
            ulonglong2 bv = *(const ulonglong2*)&Bs[k*68 + tx4];
            ull a0 = dup2(av.x), a1 = dup2(av.y), a2 = dup2(av.z), a3 = dup2(av.w);
            ffma2(acc[0][0], a0, bv.x); ffma2(acc[0][1], a0, bv.y);
            ffma2(acc[1][0], a1, bv.x); ffma2(acc[1][1], a1, bv.y);
            ffma2(acc[2][0], a2, bv.x); ffma2(acc[2][1], a2, bv.y);
            ffma2(acc[3][0], a3, bv.x); ffma2(acc[3][1], a3, bv.y);
        }
        __syncthreads();
    }
    int cc = cc0 + tx4;
    if (cc < ccmax) {
        float4 bb = bias ? *(const float4*)&bias[cc] : make_float4(0.f,0.f,0.f,0.f);
        #pragma unroll
        for (int r = 0; r < 4; r++) {
            float2 lo = unpk(acc[r][0]), hi = unpk(acc[r][1]);
            float4 v = make_float4(lo.x*scale + bb.x, lo.y*scale + bb.y,
                                   hi.x*scale + bb.z, hi.y*scale + bb.w);
            *(float4*)&C[(size_t)(cr0 + ty4 + r)*ldc + cc] = v;
        }
    }
}

// ============ h = A @ W + bias  (grid 5 x 32 -> 160 CTAs) ============
__global__ void __launch_bounds__(128) k_h(
    const float* __restrict__ Aext, int use_gf,
    const float* __restrict__ W, const float* __restrict__ bias,
    int K, int lay)
{
    if (blockIdx.x == 0 && blockIdx.y == 0 && threadIdx.x < 2)
        g_sum[lay*2 + threadIdx.x] = 0.f;
    const float* A = use_gf ? g_f : Aext;
    gemm32(A, K, blockIdx.y*32, K,
           W, MEMD, blockIdx.x*64, MEMD,
           g_h, MEMD, blockIdx.y*32, blockIdx.x*64, MEMD, bias, 1.f);
}

// ============ s = h @ [a1w_top | a1w_bot] (+a1b)  (grid 2 x 32 -> 64 CTAs) ============
__global__ void __launch_bounds__(128) k_s(
    const float* __restrict__ a1w, const float* __restrict__ a1b)
{
    int ct = blockIdx.x;
    gemm32(g_h, MEMD, blockIdx.y*32, MEMD,
           a1w + ct*MEMD*HIDD, HIDD, 0, HIDD,
           g_s, 128, blockIdx.y*32, ct*64, 128,
           ct == 0 ? a1b : (const float*)0, 1.f);
}

// ===== u = exp(masked leaky(e)) + batch sum  (R7 version: 64x64, 256 thr, coalesced) =====
__global__ void __launch_bounds__(256) k_e(
    const float* __restrict__ adj, const float* __restrict__ a2w,
    const float* __restrict__ a2b, int lay)
{
    __shared__ __align__(16) float Si[64][68];   // [h][i_local]
    __shared__ __align__(16) float Sj[64][68];   // [h][j_local]
    __shared__ float Wv[64];
    __shared__ float red[256];
    int tx = threadIdx.x & 15, ty = threadIdx.x >> 4;
    int tid = threadIdx.x;
    int b = blockIdx.z;
    int i0 = blockIdx.y * 64, j0 = blockIdx.x * 64;
    if (tid < 64) Wv[tid] = a2w[tid];
    #pragma unroll
    for (int p = 0; p < 16; p++) {
        int idx = tid + p*256;
        int h = idx & 63, r = idx >> 6;          // h-fast: coalesced LDG from g_s
        Si[h][r] = g_s[(size_t)(b*NPTS + i0 + r)*128 + h];
        Sj[h][r] = g_s[(size_t)(b*NPTS + j0 + r)*128 + 64 + h];
    }
    __syncthreads();
    float acc[4][4] = {};
    int ty4 = ty*4, tx4 = tx*4;
    #pragma unroll 4
    for (int h = 0; h < 64; h++) {
        float w = Wv[h];
        float4 si = *(const float4*)&Si[h][ty4];
        float4 sj = *(const float4*)&Sj[h][tx4];
        float siv[4] = {si.x, si.y, si.z, si.w};
        float sjv[4] = {sj.x, sj.y, sj.z, sj.w};
        #pragma unroll
        for (int di = 0; di < 4; di++)
            #pragma unroll
            for (int dj = 0; dj < 4; dj++)
                acc[di][dj] = fmaf(fmaxf(siv[di] + sjv[dj], 0.f), w, acc[di][dj]);
    }
    float ab = a2b[0];
    float lsum = 0.f;
    #pragma unroll
    for (int di = 0; di < 4; di++) {
        int i = i0 + ty4 + di;
        float4 av = *(const float4*)&adj[(size_t)(b*NPTS + i)*NPTS + j0 + tx4];
        float am[4] = {av.x, av.y, av.z, av.w};
        float o[4];
        #pragma unroll
        for (int dj = 0; dj < 4; dj++) {
            float e = acc[di][dj] + ab;
            e = (e > 0.f) ? e : NEG * e;
            float lg = e * am[dj] + (1.f - am[dj]) * (-1e30f);
            o[dj] = __expf(lg);                  // masked -> exactly 0
        }
        *(float4*)&g_u[(size_t)b*NN + i*NPTS + j0 + tx4] =
            make_float4(o[0], o[1], o[2], o[3]);
        lsum += (o[0] + o[1]) + (o[2] + o[3]);
    }
    red[tid] = lsum;
    __syncthreads();
    for (int s = 128; s > 0; s >>= 1) {
        if (tid < s) red[tid] += red[tid + s];
        __syncthreads();
    }
    if (tid == 0) atomicAdd(&g_sum[lay*2 + b], red[0]);
}

// ============ out = (U @ h) * (1/sum)  (grid 5 x 16 x 2 -> 160 CTAs) ============
__global__ void __launch_bounds__(128) k_out(float* __restrict__ out, int to_gf, int lay)
{
    int b = blockIdx.z;
    float inv = 1.f / g_sum[lay*2 + b];
    float* dst = (to_gf ? g_f : out) + (size_t)b*NPTS*MEMD;
    gemm32(g_u + (size_t)b*NN, NPTS, blockIdx.y*32, NPTS,
           g_h + (size_t)b*NPTS*MEMD, MEMD, blockIdx.x*64, MEMD,
           dst, MEMD, blockIdx.y*32, blockIdx.x*64, MEMD,
           (const float*)0, inv);
}

// ---------------- host ----------------
extern "C" void kernel_launch(void* const* d_in, const int* in_sizes, int n_in,
                              void* d_out, int out_size) {
    const float* feature = (const float*)d_in[0];
    const float* adj     = (const float*)d_in[1];
    const float* w0      = (const float*)d_in[2];
    const float* b0      = (const float*)d_in[3];
    const float* w1      = (const float*)d_in[4];
    const float* b1      = (const float*)d_in[5];
    const float* a1w     = (const float*)d_in[6];
    const float* a1b     = (const float*)d_in[7];
    const float* a2w     = (const float*)d_in[8];
    const float* a2b     = (const float*)d_in[9];
    float* out = (float*)d_out;

    dim3 gh(5, 32);          // 160 CTAs, 640 warps
    dim3 gs(2, 32);          // 64 CTAs
    dim3 ge(8, 8, BQ);       // 128 CTAs x 256 thr  (R7 config)
    dim3 go(5, 16, BQ);      // 160 CTAs, 640 warps

    // ---- layer 0 ----
    k_h  <<<gh, 128>>>(feature, 0, w0, b0, INDIM, 0);
    k_s  <<<gs, 128>>>(a1w, a1b);
    k_e  <<<ge, 256>>>(adj, a2w, a2b, 0);
    k_out<<<go, 128>>>(out, 1, 0);               // -> g_f

    // ---- layer 1 ----
    k_h  <<<gh, 128>>>(nullptr, 1, w1, b1, MEMD, 1);
    k_s  <<<gs, 128>>>(a1w, a1b);
    k_e  <<<ge, 128 + 128>>>(adj, a2w, a2b, 1);
    k_out<<<go, 128>>>(out, 0, 1);               // -> d_out
}

// round 12
// speedup vs baseline: 2.0853x; 2.0853x over previous
#include <cuda_runtime.h>

#define BQ 2
#define NPTS 512
#define INDIM 512
#define MEMD 300
#define HIDD 64
#define NEG 0.01f
#define NN (NPTS*NPTS)

typedef unsigned long long ull;

// ---------------- scratch (K-split partial buffers) ----------------
__device__ float g_hp0[1024*MEMD], g_hp1[1024*MEMD];   // h partials
__device__ float g_sp0[1024*128],  g_sp1[1024*128];    // s partials
__device__ float g_op0[1024*MEMD], g_op1[1024*MEMD];   // out partials
__device__ float g_u[BQ*NN];
__device__ float g_sum[4];     // [layer][batch]

// ---------------- f32x2 helpers ----------------
__device__ __forceinline__ ull dup2(float x) {
    ull r; asm("mov.b64 %0, {%1,%1};" : "=l"(r) : "f"(x)); return r;
}
__device__ __forceinline__ void ffma2(ull& d, ull a, ull b) {
    asm("fma.rn.f32x2 %0, %1, %2, %0;" : "+l"(d) : "l"(a), "l"(b));
}
__device__ __forceinline__ float2 unpk(ull v) {
    float2 r; asm("mov.b64 {%0,%1}, %2;" : "=f"(r.x), "=f"(r.y) : "l"(v)); return r;
}

// ====== GEMM core (R6 body): 32x64 tile, 128 thr, 4x4 micro, f32x2 ======
// Computes over k in [klo, khi). A = (A1 [+ A2]) * ascale ; B = B1 [+ B2].
// C[cr0..+32, cc0..+64] = cscale * acc + bias
__device__ __forceinline__ void gemm32(
    const float* __restrict__ A1, const float* __restrict__ A2, float ascale,
    int lda, int ar0, int klo, int khi,
    const float* __restrict__ B1, const float* __restrict__ B2,
    int ldb, int bc0, int bcmax,
    float* __restrict__ C, int ldc, int cr0, int cc0, int ccmax,
    const float* __restrict__ bias, float cscale)
{
    __shared__ __align__(16) float As[16*36];   // [k][row], stride 36
    __shared__ __align__(16) float Bs[16*68];   // [k][col], stride 68
    int tid = threadIdx.x;
    int tx = tid & 15, ty = tid >> 4;           // tx: col-quad(16), ty: row-quad(8)
    int ty4 = ty*4, tx4 = tx*4;
    ull acc[4][2] = {};                         // [row][colpair]
    for (int k0 = klo; k0 < khi; k0 += 16) {
        #pragma unroll
        for (int p = 0; p < 4; p++) {           // A: 32 rows x 16 k
            int idx = tid + p*128;
            int kk = idx & 15, r = idx >> 4;
            int ac = k0 + kk;
            float v = 0.f;
            if (ac < khi) {
                size_t o = (size_t)(ar0 + r)*lda + ac;
                v = A1[o];
                if (A2) v += A2[o];
                v *= ascale;
            }
            As[kk*36 + r] = v;
        }
        #pragma unroll
        for (int p = 0; p < 8; p++) {           // B: 16 k x 64 cols
            int idx = tid + p*128;
            int c = idx & 63, kb = idx >> 6;
            int bk = k0 + kb, bc = bc0 + c;
            float v = 0.f;
            if (bk < khi && bc < bcmax) {
                size_t o = (size_t)bk*ldb + bc;
                v = B1[o];
                if (B2) v += B2[o];
            }
            Bs[kb*68 + c] = v;
        }
        __syncthreads();
        #pragma unroll
        for (int k = 0; k < 16; k++) {
            float4 av = *(const float4*)&As[k*36 + ty4];
            ulonglong2 bv = *(const ulonglong2*)&Bs[k*68 + tx4];
            ull a0 = dup2(av.x), a1 = dup2(av.y), a2 = dup2(av.z), a3 = dup2(av.w);
            ffma2(acc[0][0], a0, bv.x); ffma2(acc[0][1], a0, bv.y);
            ffma2(acc[1][0], a1, bv.x); ffma2(acc[1][1], a1, bv.y);
            ffma2(acc[2][0], a2, bv.x); ffma2(acc[2][1], a2, bv.y);
            ffma2(acc[3][0], a3, bv.x); ffma2(acc[3][1], a3, bv.y);
        }
        __syncthreads();
    }
    int cc = cc0 + tx4;
    if (cc < ccmax) {
        float4 bb = bias ? *(const float4*)&bias[cc] : make_float4(0.f,0.f,0.f,0.f);
        #pragma unroll
        for (int r = 0; r < 4; r++) {
            float2 lo = unpk(acc[r][0]), hi = unpk(acc[r][1]);
            float4 v = make_float4(lo.x*cscale + bb.x, lo.y*cscale + bb.y,
                                   hi.x*cscale + bb.z, hi.y*cscale + bb.w);
            *(float4*)&C[(size_t)(cr0 + ty4 + r)*ldc + cc] = v;
        }
    }
}

// ====== h partials = A @ W (+bias on split0)  grid (5, 32, 2splits) ======
// use_comb=0: A = Aext.  use_comb=1: A = (g_op0+g_op1) * (1/g_sum[b])  (layer-0 out)
__global__ void __launch_bounds__(128) k_h(
    const float* __restrict__ Aext, int use_comb,
    const float* __restrict__ W, const float* __restrict__ bias,
    int Ktot, int lay)
{
    int sp = blockIdx.z;
    if (sp == 0 && blockIdx.x == 0 && blockIdx.y == 0 && threadIdx.x < 2)
        g_sum[lay*2 + threadIdx.x] = 0.f;
    int khalf = (Ktot + 1) >> 1;
    int klo = sp * khalf, khi = min(Ktot, klo + khalf);
    int ar0 = blockIdx.y * 32;
    const float *A1, *A2; float ascale; int lda;
    if (use_comb) {
        A1 = g_op0; A2 = g_op1; lda = MEMD;
        ascale = 1.f / g_sum[(ar0 >> 9)];        // layer-0 softmax sums
    } else {
        A1 = Aext; A2 = (const float*)0; lda = Ktot; ascale = 1.f;
    }
    float* C = sp ? g_hp1 : g_hp0;
    gemm32(A1, A2, ascale, lda, ar0, klo, khi,
           W, (const float*)0, MEMD, blockIdx.x*64, MEMD,
           C, MEMD, ar0, blockIdx.x*64, MEMD,
           sp == 0 ? bias : (const float*)0, 1.f);
}

// ====== s partials = (hp0+hp1) @ a1w_half (+a1b on si/split0)  grid (2, 32, 2) ======
__global__ void __launch_bounds__(128) k_s(
    const float* __restrict__ a1w, const float* __restrict__ a1b)
{
    int ct = blockIdx.x, sp = blockIdx.z;
    int khalf = (MEMD + 1) >> 1;                 // 150
    int klo = sp * khalf, khi = min(MEMD, klo + khalf);
    float* C = sp ? g_sp1 : g_sp0;
    gemm32(g_hp0, g_hp1, 1.f, MEMD, blockIdx.y*32, klo, khi,
           a1w + (size_t)ct*MEMD*HIDD, (const float*)0, HIDD, 0, HIDD,
           C, 128, blockIdx.y*32, ct*64, 128,
           (ct == 0 && sp == 0) ? a1b : (const float*)0, 1.f);
}

// ====== u = exp(masked leaky(e)) + batch sum  (64x64, 256 thr)  grid (8,8,2) ======
__global__ void __launch_bounds__(256) k_e(
    const float* __restrict__ adj, const float* __restrict__ a2w,
    const float* __restrict__ a2b, int lay)
{
    __shared__ __align__(16) float Si[64][68];   // [h][i_local]
    __shared__ __align__(16) float Sj[64][68];   // [h][j_local]
    __shared__ float Wv[64];
    __shared__ float red[256];
    int tx = threadIdx.x & 15, ty = threadIdx.x >> 4;
    int tid = threadIdx.x;
    int b = blockIdx.z;
    int i0 = blockIdx.y * 64, j0 = blockIdx.x * 64;
    if (tid < 64) Wv[tid] = a2w[tid];
    #pragma unroll
    for (int p = 0; p < 16; p++) {
        int idx = tid + p*256;
        int h = idx & 63, r = idx >> 6;          // h-fast: coalesced
        size_t oi = (size_t)(b*NPTS + i0 + r)*128 + h;
        size_t oj = (size_t)(b*NPTS + j0 + r)*128 + 64 + h;
        Si[h][r] = g_sp0[oi] + g_sp1[oi];
        Sj[h][r] = g_sp0[oj] + g_sp1[oj];
    }
    __syncthreads();
    float acc[4][4] = {};
    int ty4 = ty*4, tx4 = tx*4;
    #pragma unroll 4
    for (int h = 0; h < 64; h++) {
        float w = Wv[h];
        float4 si = *(const float4*)&Si[h][ty4];
        float4 sj = *(const float4*)&Sj[h][tx4];
        float siv[4] = {si.x, si.y, si.z, si.w};
        float sjv[4] = {sj.x, sj.y, sj.z, sj.w};
        #pragma unroll
        for (int di = 0; di < 4; di++)
            #pragma unroll
            for (int dj = 0; dj < 4; dj++)
                acc[di][dj] = fmaf(fmaxf(siv[di] + sjv[dj], 0.f), w, acc[di][dj]);
    }
    float ab = a2b[0];
    float lsum = 0.f;
    #pragma unroll
    for (int di = 0; di < 4; di++) {
        int i = i0 + ty4 + di;
        float4 av = *(const float4*)&adj[(size_t)(b*NPTS + i)*NPTS + j0 + tx4];
        float am[4] = {av.x, av.y, av.z, av.w};
        float o[4];
        #pragma unroll
        for (int dj = 0; dj < 4; dj++) {
            float e = acc[di][dj] + ab;
            e = (e > 0.f) ? e : NEG * e;
            float lg = e * am[dj] + (1.f - am[dj]) * (-1e30f);
            o[dj] = __expf(lg);                  // masked -> exactly 0
        }
        *(float4*)&g_u[(size_t)b*NN + i*NPTS + j0 + tx4] =
            make_float4(o[0], o[1], o[2], o[3]);
        lsum += (o[0] + o[1]) + (o[2] + o[3]);
    }
    red[tid] = lsum;
    __syncthreads();
    for (int s = 128; s > 0; s >>= 1) {
        if (tid < s) red[tid] += red[tid + s];
        __syncthreads();
    }
    if (tid == 0) atomicAdd(&g_sum[lay*2 + b], red[0]);
}

// ====== out partials = U @ (hp0+hp1)  grid (5, 16, 4: b*2+split) ======
__global__ void __launch_bounds__(128) k_out()
{
    int b = blockIdx.z >> 1, sp = blockIdx.z & 1;
    int klo = sp * 256, khi = klo + 256;
    float* C = sp ? g_op1 : g_op0;
    size_t hoff = (size_t)b*NPTS*MEMD;
    gemm32(g_u + (size_t)b*NN, (const float*)0, 1.f, NPTS, blockIdx.y*32, klo, khi,
           g_hp0 + hoff, g_hp1 + hoff, MEMD, blockIdx.x*64, MEMD,
           C, MEMD, b*NPTS + blockIdx.y*32, blockIdx.x*64, MEMD,
           (const float*)0, 1.f);
}

// ====== final combine (layer 1): out = (op0+op1) * (1/g_sum[2+b]) ======
__global__ void __launch_bounds__(256) k_comb(float* __restrict__ out)
{
    int t4 = blockIdx.x * 256 + threadIdx.x;     // 76800 float4s (300 = 75*4 per row)
    int row = t4 / 75;
    float inv = 1.f / g_sum[2 + (row >> 9)];
    float4 a = *(const float4*)&g_op0[(size_t)t4*4];
    float4 c = *(const float4*)&g_op1[(size_t)t4*4];
    float4 v = make_float4((a.x+c.x)*inv, (a.y+c.y)*inv,
                           (a.z+c.z)*inv, (a.w+c.w)*inv);
    *(float4*)&out[(size_t)t4*4] = v;
}

// ---------------- host ----------------
extern "C" void kernel_launch(void* const* d_in, const int* in_sizes, int n_in,
                              void* d_out, int out_size) {
    const float* feature = (const float*)d_in[0];
    const float* adj     = (const float*)d_in[1];
    const float* w0      = (const float*)d_in[2];
    const float* b0      = (const float*)d_in[3];
    const float* w1      = (const float*)d_in[4];
    const float* b1      = (const float*)d_in[5];
    const float* a1w     = (const float*)d_in[6];
    const float* a1b     = (const float*)d_in[7];
    const float* a2w     = (const float*)d_in[8];
    const float* a2b     = (const float*)d_in[9];
    float* out = (float*)d_out;

    dim3 gh(5, 32, 2);       // 320 CTAs
    dim3 gs(2, 32, 2);       // 128 CTAs
    dim3 ge(8, 8, BQ);       // 128 CTAs x 256 thr
    dim3 go(5, 16, 4);       // 320 CTAs (b x split)

    // ---- layer 0 ----
    k_h   <<<gh, 128>>>(feature, 0, w0, b0, INDIM, 0);
    k_s   <<<gs, 128>>>(a1w, a1b);
    k_e   <<<ge, 256>>>(adj, a2w, a2b, 0);
    k_out <<<go, 128>>>();

    // ---- layer 1 (k_h combines layer-0 out partials with 1/sum on the fly) ----
    k_h   <<<gh, 128>>>(nullptr, 1, w1, b1, MEMD, 1);
    k_s   <<<gs, 128>>>(a1w, a1b);
    k_e   <<<ge, 256>>>(adj, a2w, a2b, 1);
    k_out <<<go, 128>>>();
    k_comb<<<300, 256>>>(out);
}

// round 13
// speedup vs baseline: 2.0895x; 1.0020x over previous
#include <cuda_runtime.h>

#define BQ 2
#define NPTS 512
#define INDIM 512
#define MEMD 300
#define HIDD 64
#define NEG 0.01f
#define NN (NPTS*NPTS)

typedef unsigned long long ull;

// ---------------- scratch (K-split partial buffers) ----------------
__device__ float g_hp0[1024*MEMD], g_hp1[1024*MEMD];   // h partials
__device__ float g_sp0[1024*128],  g_sp1[1024*128];    // s partials
__device__ float g_op0[1024*MEMD], g_op1[1024*MEMD];   // out partials
__device__ float g_u[BQ*NN];
__device__ float g_sum[4];     // [layer][batch]

// ---------------- f32x2 helpers ----------------
__device__ __forceinline__ ull dup2(float x) {
    ull r; asm("mov.b64 %0, {%1,%1};" : "=l"(r) : "f"(x)); return r;
}
__device__ __forceinline__ void ffma2(ull& d, ull a, ull b) {
    asm("fma.rn.f32x2 %0, %1, %2, %0;" : "+l"(d) : "l"(a), "l"(b));
}
__device__ __forceinline__ float2 unpk(ull v) {
    float2 r; asm("mov.b64 {%0,%1}, %2;" : "=f"(r.x), "=f"(r.y) : "l"(v)); return r;
}

// ====== GEMM core: 32x64 tile, 128 thr, 4x4 micro, f32x2 ======
// Double-buffered smem, branch-free clamped prefetch (LDG overlaps compute).
// Computes over k in [klo, khi). A = (A1 [+ A2]) * ascale ; B = B1 [+ B2].
// C[cr0..+32, cc0..+64] = cscale * acc + bias
__device__ __forceinline__ void gemm32(
    const float* __restrict__ A1, const float* __restrict__ A2, float ascale,
    int lda, int ar0, int klo, int khi,
    const float* __restrict__ B1, const float* __restrict__ B2,
    int ldb, int bc0, int bcmax,
    float* __restrict__ C, int ldc, int cr0, int cc0, int ccmax,
    const float* __restrict__ bias, float cscale)
{
    __shared__ __align__(16) float As[2][16*36];   // [buf][k][row], stride 36
    __shared__ __align__(16) float Bs[2][16*68];   // [buf][k][col], stride 68
    int tid = threadIdx.x;
    int tx = tid & 15, ty = tid >> 4;              // tx: col-quad(16), ty: row-quad(8)
    int ty4 = ty*4, tx4 = tx*4;
    int kA = tid & 15, rA = tid >> 4;              // A stage: 4/thread, rows rA+8p
    int cB = tid & 63, kB = tid >> 6;              // B stage: 8/thread, k = kB+2p
    int bcs = bc0 + cB;
    int bcc = min(bcs, bcmax - 1);
    float bval = (bcs < bcmax) ? 1.f : 0.f;
    ull acc[4][2] = {};                            // [row][colpair]
    float ra[4], rb[8];

    // ---- load chunk 0 into regs, then buf 0 ----
    #pragma unroll
    for (int p = 0; p < 4; p++) {
        int k = klo + kA;
        int kc = min(k, khi - 1);
        size_t o = (size_t)(ar0 + rA + 8*p)*lda + kc;
        float v = A1[o];
        if (A2) v += A2[o];
        ra[p] = (k < khi) ? v * ascale : 0.f;
    }
    #pragma unroll
    for (int p = 0; p < 8; p++) {
        int k = klo + kB + 2*p;
        int kc = min(k, khi - 1);
        size_t o = (size_t)kc*ldb + bcc;
        float v = B1[o];
        if (B2) v += B2[o];
        rb[p] = (k < khi) ? v * bval : 0.f;
    }
    #pragma unroll
    for (int p = 0; p < 4; p++) As[0][kA*36 + rA + 8*p] = ra[p];
    #pragma unroll
    for (int p = 0; p < 8; p++) Bs[0][(kB + 2*p)*68 + cB] = rb[p];
    __syncthreads();

    int nch = (khi - klo + 15) >> 4;
    for (int c = 0; c < nch; c++) {
        // ---- issue prefetch for chunk c+1 (clamped; zeroed past end) ----
        int kn = klo + (c + 1)*16;
        #pragma unroll
        for (int p = 0; p < 4; p++) {
            int k = kn + kA;
            int kc = min(k, khi - 1);
            size_t o = (size_t)(ar0 + rA + 8*p)*lda + kc;
            float v = A1[o];
            if (A2) v += A2[o];
            ra[p] = (k < khi) ? v * ascale : 0.f;
        }
        #pragma unroll
        for (int p = 0; p < 8; p++) {
            int k = kn + kB + 2*p;
            int kc = min(k, khi - 1);
            size_t o = (size_t)kc*ldb + bcc;
            float v = B1[o];
            if (B2) v += B2[o];
            rb[p] = (k < khi) ? v * bval : 0.f;
        }
        // ---- compute chunk c (overlaps the LDGs above) ----
        const float* as = As[c & 1];
        const float* bs = Bs[c & 1];
        #pragma unroll
        for (int k = 0; k < 16; k++) {
            float4 av = *(const float4*)&as[k*36 + ty4];
            ulonglong2 bv = *(const ulonglong2*)&bs[k*68 + tx4];
            ull a0 = dup2(av.x), a1 = dup2(av.y), a2 = dup2(av.z), a3 = dup2(av.w);
            ffma2(acc[0][0], a0, bv.x); ffma2(acc[0][1], a0, bv.y);
            ffma2(acc[1][0], a1, bv.x); ffma2(acc[1][1], a1, bv.y);
            ffma2(acc[2][0], a2, bv.x); ffma2(acc[2][1], a2, bv.y);
            ffma2(acc[3][0], a3, bv.x); ffma2(acc[3][1], a3, bv.y);
        }
        // ---- store chunk c+1 into the other buffer (free since c-1 done) ----
        float* asn = As[(c + 1) & 1];
        float* bsn = Bs[(c + 1) & 1];
        #pragma unroll
        for (int p = 0; p < 4; p++) asn[kA*36 + rA + 8*p] = ra[p];
        #pragma unroll
        for (int p = 0; p < 8; p++) bsn[(kB + 2*p)*68 + cB] = rb[p];
        __syncthreads();
    }
    int cc = cc0 + tx4;
    if (cc < ccmax) {
        float4 bb = bias ? *(const float4*)&bias[cc] : make_float4(0.f,0.f,0.f,0.f);
        #pragma unroll
        for (int r = 0; r < 4; r++) {
            float2 lo = unpk(acc[r][0]), hi = unpk(acc[r][1]);
            float4 v = make_float4(lo.x*cscale + bb.x, lo.y*cscale + bb.y,
                                   hi.x*cscale + bb.z, hi.y*cscale + bb.w);
            *(float4*)&C[(size_t)(cr0 + ty4 + r)*ldc + cc] = v;
        }
    }
}

// ====== h partials = A @ W (+bias on split0)  grid (5, 32, 2splits) ======
__global__ void __launch_bounds__(128) k_h(
    const float* __restrict__ Aext, int use_comb,
    const float* __restrict__ W, const float* __restrict__ bias,
    int Ktot, int lay)
{
    int sp = blockIdx.z;
    if (sp == 0 && blockIdx.x == 0 && blockIdx.y == 0 && threadIdx.x < 2)
        g_sum[lay*2 + threadIdx.x] = 0.f;
    int khalf = (Ktot + 1) >> 1;
    int klo = sp * khalf, khi = min(Ktot, klo + khalf);
    int ar0 = blockIdx.y * 32;
    const float *A1, *A2; float ascale; int lda;
    if (use_comb) {
        A1 = g_op0; A2 = g_op1; lda = MEMD;
        ascale = 1.f / g_sum[(ar0 >> 9)];        // layer-0 softmax sums
    } else {
        A1 = Aext; A2 = (const float*)0; lda = Ktot; ascale = 1.f;
    }
    float* C = sp ? g_hp1 : g_hp0;
    gemm32(A1, A2, ascale, lda, ar0, klo, khi,
           W, (const float*)0, MEMD, blockIdx.x*64, MEMD,
           C, MEMD, ar0, blockIdx.x*64, MEMD,
           sp == 0 ? bias : (const float*)0, 1.f);
}

// ====== s partials = (hp0+hp1) @ a1w_half (+a1b on si/split0)  grid (2, 32, 2) ======
__global__ void __launch_bounds__(128) k_s(
    const float* __restrict__ a1w, const float* __restrict__ a1b)
{
    int ct = blockIdx.x, sp = blockIdx.z;
    int khalf = (MEMD + 1) >> 1;                 // 150
    int klo = sp * khalf, khi = min(MEMD, klo + khalf);
    float* C = sp ? g_sp1 : g_sp0;
    gemm32(g_hp0, g_hp1, 1.f, MEMD, blockIdx.y*32, klo, khi,
           a1w + (size_t)ct*MEMD*HIDD, (const float*)0, HIDD, 0, HIDD,
           C, 128, blockIdx.y*32, ct*64, 128,
           (ct == 0 && sp == 0) ? a1b : (const float*)0, 1.f);
}

// ====== u = exp(masked leaky(e)) + batch sum  (64x64, 256 thr)  grid (8,8,2) ======
__global__ void __launch_bounds__(256) k_e(
    const float* __restrict__ adj, const float* __restrict__ a2w,
    const float* __restrict__ a2b, int lay)
{
    __shared__ __align__(16) float Si[64][68];   // [h][i_local]
    __shared__ __align__(16) float Sj[64][68];   // [h][j_local]
    __shared__ float Wv[64];
    __shared__ float red[256];
    int tx = threadIdx.x & 15, ty = threadIdx.x >> 4;
    int tid = threadIdx.x;
    int b = blockIdx.z;
    int i0 = blockIdx.y * 64, j0 = blockIdx.x * 64;
    if (tid < 64) Wv[tid] = a2w[tid];
    #pragma unroll
    for (int p = 0; p < 16; p++) {
        int idx = tid + p*256;
        int h = idx & 63, r = idx >> 6;          // h-fast: coalesced
        size_t oi = (size_t)(b*NPTS + i0 + r)*128 + h;
        size_t oj = (size_t)(b*NPTS + j0 + r)*128 + 64 + h;
        Si[h][r] = g_sp0[oi] + g_sp1[oi];
        Sj[h][r] = g_sp0[oj] + g_sp1[oj];
    }
    __syncthreads();
    float acc[4][4] = {};
    int ty4 = ty*4, tx4 = tx*4;
    #pragma unroll 4
    for (int h = 0; h < 64; h++) {
        float w = Wv[h];
        float4 si = *(const float4*)&Si[h][ty4];
        float4 sj = *(const float4*)&Sj[h][tx4];
        float siv[4] = {si.x, si.y, si.z, si.w};
        float sjv[4] = {sj.x, sj.y, sj.z, sj.w};
        #pragma unroll
        for (int di = 0; di < 4; di++)
            #pragma unroll
            for (int dj = 0; dj < 4; dj++)
                acc[di][dj] = fmaf(fmaxf(siv[di] + sjv[dj], 0.f), w, acc[di][dj]);
    }
    float ab = a2b[0];
    float lsum = 0.f;
    #pragma unroll
    for (int di = 0; di < 4; di++) {
        int i = i0 + ty4 + di;
        float4 av = *(const float4*)&adj[(size_t)(b*NPTS + i)*NPTS + j0 + tx4];
        float am[4] = {av.x, av.y, av.z, av.w};
        float o[4];
        #pragma unroll
        for (int dj = 0; dj < 4; dj++) {
            float e = acc[di][dj] + ab;
            e = (e > 0.f) ? e : NEG * e;
            float lg = e * am[dj] + (1.f - am[dj]) * (-1e30f);
            o[dj] = __expf(lg);                  // masked -> exactly 0
        }
        *(float4*)&g_u[(size_t)b*NN + i*NPTS + j0 + tx4] =
            make_float4(o[0], o[1], o[2], o[3]);
        lsum += (o[0] + o[1]) + (o[2] + o[3]);
    }
    red[tid] = lsum;
    __syncthreads();
    for (int s = 128; s > 0; s >>= 1) {
        if (tid < s) red[tid] += red[tid + s];
        __syncthreads();
    }
    if (tid == 0) atomicAdd(&g_sum[lay*2 + b], red[0]);
}

// ====== out partials = U @ (hp0+hp1)  grid (5, 16, 4: b*2+split) ======
__global__ void __launch_bounds__(128) k_out()
{
    int b = blockIdx.z >> 1, sp = blockIdx.z & 1;
    int klo = sp * 256, khi = klo + 256;
    float* C = sp ? g_op1 : g_op0;
    size_t hoff = (size_t)b*NPTS*MEMD;
    gemm32(g_u + (size_t)b*NN, (const float*)0, 1.f, NPTS, blockIdx.y*32, klo, khi,
           g_hp0 + hoff, g_hp1 + hoff, MEMD, blockIdx.x*64, MEMD,
           C, MEMD, b*NPTS + blockIdx.y*32, blockIdx.x*64, MEMD,
           (const float*)0, 1.f);
}

// ====== final combine (layer 1): out = (op0+op1) * (1/g_sum[2+b]) ======
__global__ void __launch_bounds__(256) k_comb(float* __restrict__ out)
{
    int t4 = blockIdx.x * 256 + threadIdx.x;     // 76800 float4s
    int row = t4 / 75;
    float inv = 1.f / g_sum[2 + (row >> 9)];
    float4 a = *(const float4*)&g_op0[(size_t)t4*4];
    float4 c = *(const float4*)&g_op1[(size_t)t4*4];
    float4 v = make_float4((a.x+c.x)*inv, (a.y+c.y)*inv,
                           (a.z+c.z)*inv, (a.w+c.w)*inv);
    *(float4*)&out[(size_t)t4*4] = v;
}

// ---------------- host ----------------
extern "C" void kernel_launch(void* const* d_in, const int* in_sizes, int n_in,
                              void* d_out, int out_size) {
    const float* feature = (const float*)d_in[0];
    const float* adj     = (const float*)d_in[1];
    const float* w0      = (const float*)d_in[2];
    const float* b0      = (const float*)d_in[3];
    const float* w1      = (const float*)d_in[4];
    const float* b1      = (const float*)d_in[5];
    const float* a1w     = (const float*)d_in[6];
    const float* a1b     = (const float*)d_in[7];
    const float* a2w     = (const float*)d_in[8];
    const float* a2b     = (const float*)d_in[9];
    float* out = (float*)d_out;

    dim3 gh(5, 32, 2);       // 320 CTAs
    dim3 gs(2, 32, 2);       // 128 CTAs
    dim3 ge(8, 8, BQ);       // 128 CTAs x 256 thr
    dim3 go(5, 16, 4);       // 320 CTAs (b x split)

    // ---- layer 0 ----
    k_h   <<<gh, 128>>>(feature, 0, w0, b0, INDIM, 0);
    k_s   <<<gs, 128>>>(a1w, a1b);
    k_e   <<<ge, 256>>>(adj, a2w, a2b, 0);
    k_out <<<go, 128>>>();

    // ---- layer 1 (k_h combines layer-0 out partials with 1/sum on the fly) ----
    k_h   <<<gh, 128>>>(nullptr, 1, w1, b1, MEMD, 1);
    k_s   <<<gs, 128>>>(a1w, a1b);
    k_e   <<<ge, 256>>>(adj, a2w, a2b, 1);
    k_out <<<go, 128>>>();
    k_comb<<<300, 256>>>(out);
}

// round 14
// speedup vs baseline: 2.1308x; 1.0197x over previous
#include <cuda_runtime.h>

#define BQ 2
#define NPTS 512
#define INDIM 512
#define MEMD 300
#define HIDD 64
#define NEG 0.01f
#define NN (NPTS*NPTS)

typedef unsigned long long ull;

// ---------------- scratch (4-way K-split partials) ----------------
__device__ float g_hp0[1024*MEMD], g_hp1[1024*MEMD], g_hp2[1024*MEMD], g_hp3[1024*MEMD];
__device__ float g_sp0[1024*128],  g_sp1[1024*128],  g_sp2[1024*128],  g_sp3[1024*128];
__device__ float g_op0[1024*MEMD], g_op1[1024*MEMD], g_op2[1024*MEMD], g_op3[1024*MEMD];
__device__ float g_u[BQ*NN];
__device__ float g_sum[4];     // [layer][batch]

// ---------------- f32x2 helpers ----------------
__device__ __forceinline__ ull dup2(float x) {
    ull r; asm("mov.b64 %0, {%1,%1};" : "=l"(r) : "f"(x)); return r;
}
__device__ __forceinline__ void ffma2(ull& d, ull a, ull b) {
    asm("fma.rn.f32x2 %0, %1, %2, %0;" : "+l"(d) : "l"(a), "l"(b));
}
__device__ __forceinline__ float2 unpk(ull v) {
    float2 r; asm("mov.b64 {%0,%1}, %2;" : "=f"(r.x), "=f"(r.y) : "l"(v)); return r;
}

// ====== GEMM core: 64x64 tile, 256 thr, 4x4 micro, f32x2 ======
// A = (A1[+A2][+A3][+A4]) * ascale ; B = B1[+B2][+B3][+B4]; k in [klo,khi)
// C[cr0..+64, cc0..+64] = cscale*acc + bias   (clamped loads; cols clamped to ccmax)
__device__ __forceinline__ void gemm64(
    const float* __restrict__ A1, const float* __restrict__ A2,
    const float* __restrict__ A3, const float* __restrict__ A4, float ascale,
    int lda, int ar0, int klo, int khi,
    const float* __restrict__ B1, const float* __restrict__ B2,
    const float* __restrict__ B3, const float* __restrict__ B4,
    int ldb, int bc0, int bcmax,
    float* __restrict__ C, int ldc, int cr0, int cc0, int ccmax,
    const float* __restrict__ bias, float cscale)
{
    __shared__ __align__(16) float As[16*68];   // [k][row], stride 68
    __shared__ __align__(16) float Bs[16*68];   // [k][col], stride 68
    int tid = threadIdx.x;
    int tx = tid & 15, ty = tid >> 4;           // tx: col-quad(16), ty: row-quad(16)
    int ty4 = ty*4, tx4 = tx*4;
    int kA = tid & 15, rA = tid >> 4;           // A stage: 4/thread, rows rA+16p
    int cB = tid & 63, kB = tid >> 6;           // B stage: 4/thread, k = kB+4p
    int bcs = bc0 + cB;
    int bcc = min(bcs, bcmax - 1);
    float bval = (bcs < bcmax) ? 1.f : 0.f;
    ull acc[4][2] = {};                         // [row][colpair]
    for (int k0 = klo; k0 < khi; k0 += 16) {
        #pragma unroll
        for (int p = 0; p < 4; p++) {           // A: 64 rows x 16 k
            int k = k0 + kA;
            int kc = min(k, khi - 1);
            size_t o = (size_t)(ar0 + rA + 16*p)*lda + kc;
            float v = A1[o];
            if (A2) v += A2[o];
            if (A3) v += A3[o];
            if (A4) v += A4[o];
            As[kA*68 + rA + 16*p] = (k < khi) ? v * ascale : 0.f;
        }
        #pragma unroll
        for (int p = 0; p < 4; p++) {           // B: 16 k x 64 cols
            int k = k0 + kB + 4*p;
            int kc = min(k, khi - 1);
            size_t o = (size_t)kc*ldb + bcc;
            float v = B1[o];
            if (B2) v += B2[o];
            if (B3) v += B3[o];
            if (B4) v += B4[o];
            Bs[(kB + 4*p)*68 + cB] = (k < khi) ? v * bval : 0.f;
        }
        __syncthreads();
        #pragma unroll
        for (int k = 0; k < 16; k++) {
            float4 av = *(const float4*)&As[k*68 + ty4];
            ulonglong2 bv = *(const ulonglong2*)&Bs[k*68 + tx4];
            ull a0 = dup2(av.x), a1 = dup2(av.y), a2 = dup2(av.z), a3 = dup2(av.w);
            ffma2(acc[0][0], a0, bv.x); ffma2(acc[0][1], a0, bv.y);
            ffma2(acc[1][0], a1, bv.x); ffma2(acc[1][1], a1, bv.y);
            ffma2(acc[2][0], a2, bv.x); ffma2(acc[2][1], a2, bv.y);
            ffma2(acc[3][0], a3, bv.x); ffma2(acc[3][1], a3, bv.y);
        }
        __syncthreads();
    }
    int cc = cc0 + tx4;
    if (cc < ccmax) {
        float4 bb = bias ? *(const float4*)&bias[cc] : make_float4(0.f,0.f,0.f,0.f);
        #pragma unroll
        for (int r = 0; r < 4; r++) {
            float2 lo = unpk(acc[r][0]), hi = unpk(acc[r][1]);
            float4 v = make_float4(lo.x*cscale + bb.x, lo.y*cscale + bb.y,
                                   hi.x*cscale + bb.z, hi.y*cscale + bb.w);
            *(float4*)&C[(size_t)(cr0 + ty4 + r)*ldc + cc] = v;
        }
    }
}

__device__ float* hp_buf(int sp) {
    return sp == 0 ? g_hp0 : sp == 1 ? g_hp1 : sp == 2 ? g_hp2 : g_hp3;
}
__device__ float* sp_buf(int sp) {
    return sp == 0 ? g_sp0 : sp == 1 ? g_sp1 : sp == 2 ? g_sp2 : g_sp3;
}
__device__ float* op_buf(int sp) {
    return sp == 0 ? g_op0 : sp == 1 ? g_op1 : sp == 2 ? g_op2 : g_op3;
}

// ====== h partials = A @ W (+bias on sp0)  grid (5, 16, 4) = 320 CTAs ======
// use_comb: A = (op0+op1+op2+op3) * (1/g_sum[b])   (layer-0 attention output)
__global__ void __launch_bounds__(256) k_h(
    const float* __restrict__ Aext, int use_comb,
    const float* __restrict__ W, const float* __restrict__ bias,
    int Ktot, int lay)
{
    int sp = blockIdx.z;
    if (sp == 0 && blockIdx.x == 0 && blockIdx.y == 0 && threadIdx.x < 2)
        g_sum[lay*2 + threadIdx.x] = 0.f;
    int kq = (Ktot + 3) >> 2;
    int klo = sp * kq, khi = min(Ktot, klo + kq);
    int ar0 = blockIdx.y * 64;
    const float *A1, *A2, *A3, *A4; float ascale; int lda;
    if (use_comb) {
        A1 = g_op0; A2 = g_op1; A3 = g_op2; A4 = g_op3; lda = MEMD;
        ascale = 1.f / g_sum[(ar0 >> 9)];      // layer-0 softmax sums
    } else {
        A1 = Aext; A2 = A3 = A4 = (const float*)0; lda = Ktot; ascale = 1.f;
    }
    gemm64(A1, A2, A3, A4, ascale, lda, ar0, klo, khi,
           W, (const float*)0, (const float*)0, (const float*)0, MEMD,
           blockIdx.x*64, MEMD,
           hp_buf(sp), MEMD, ar0, blockIdx.x*64, MEMD,
           sp == 0 ? bias : (const float*)0, 1.f);
}

// ====== s partials = (Σhp) @ a1w_half (+a1b on si/sp0)  grid (2, 16, 4) ======
__global__ void __launch_bounds__(256) k_s(
    const float* __restrict__ a1w, const float* __restrict__ a1b)
{
    int ct = blockIdx.x, sp = blockIdx.z;
    int kq = (MEMD + 3) >> 2;                  // 75
    int klo = sp * kq, khi = min(MEMD, klo + kq);
    gemm64(g_hp0, g_hp1, g_hp2, g_hp3, 1.f, MEMD, blockIdx.y*64, klo, khi,
           a1w + (size_t)ct*MEMD*HIDD, (const float*)0, (const float*)0,
           (const float*)0, HIDD, 0, HIDD,
           sp_buf(sp), 128, blockIdx.y*64, ct*64, 128,
           (ct == 0 && sp == 0) ? a1b : (const float*)0, 1.f);
}

// ====== u = exp(masked leaky(e)) + batch sum  (64x64, 256 thr)  grid (8,8,2) ======
__global__ void __launch_bounds__(256) k_e(
    const float* __restrict__ adj, const float* __restrict__ a2w,
    const float* __restrict__ a2b, int lay)
{
    __shared__ __align__(16) float Si[64][68];   // [h][i_local]
    __shared__ __align__(16) float Sj[64][68];   // [h][j_local]
    __shared__ float Wv[64];
    __shared__ float red[256];
    int tx = threadIdx.x & 15, ty = threadIdx.x >> 4;
    int tid = threadIdx.x;
    int b = blockIdx.z;
    int i0 = blockIdx.y * 64, j0 = blockIdx.x * 64;
    if (tid < 64) Wv[tid] = a2w[tid];
    #pragma unroll
    for (int p = 0; p < 16; p++) {
        int idx = tid + p*256;
        int h = idx & 63, r = idx >> 6;          // h-fast: coalesced
        size_t oi = (size_t)(b*NPTS + i0 + r)*128 + h;
        size_t oj = (size_t)(b*NPTS + j0 + r)*128 + 64 + h;
        Si[h][r] = (g_sp0[oi] + g_sp1[oi]) + (g_sp2[oi] + g_sp3[oi]);
        Sj[h][r] = (g_sp0[oj] + g_sp1[oj]) + (g_sp2[oj] + g_sp3[oj]);
    }
    __syncthreads();
    float acc[4][4] = {};
    int ty4 = ty*4, tx4 = tx*4;
    #pragma unroll 4
    for (int h = 0; h < 64; h++) {
        float w = Wv[h];
        float4 si = *(const float4*)&Si[h][ty4];
        float4 sj = *(const float4*)&Sj[h][tx4];
        float siv[4] = {si.x, si.y, si.z, si.w};
        float sjv[4] = {sj.x, sj.y, sj.z, sj.w};
        #pragma unroll
        for (int di = 0; di < 4; di++)
            #pragma unroll
            for (int dj = 0; dj < 4; dj++)
                acc[di][dj] = fmaf(fmaxf(siv[di] + sjv[dj], 0.f), w, acc[di][dj]);
    }
    float ab = a2b[0];
    float lsum = 0.f;
    #pragma unroll
    for (int di = 0; di < 4; di++) {
        int i = i0 + ty4 + di;
        float4 av = *(const float4*)&adj[(size_t)(b*NPTS + i)*NPTS + j0 + tx4];
        float am[4] = {av.x, av.y, av.z, av.w};
        float o[4];
        #pragma unroll
        for (int dj = 0; dj < 4; dj++) {
            float e = acc[di][dj] + ab;
            e = (e > 0.f) ? e : NEG * e;
            float lg = e * am[dj] + (1.f - am[dj]) * (-1e30f);
            o[dj] = __expf(lg);                  // masked -> exactly 0
        }
        *(float4*)&g_u[(size_t)b*NN + i*NPTS + j0 + tx4] =
            make_float4(o[0], o[1], o[2], o[3]);
        lsum += (o[0] + o[1]) + (o[2] + o[3]);
    }
    red[tid] = lsum;
    __syncthreads();
    for (int s = 128; s > 0; s >>= 1) {
        if (tid < s) red[tid] += red[tid + s];
        __syncthreads();
    }
    if (tid == 0) atomicAdd(&g_sum[lay*2 + b], red[0]);
}

// ====== out partials = U @ (Σhp)  grid (5, 8, 8: b*4+split) = 320 CTAs ======
__global__ void __launch_bounds__(256) k_out()
{
    int b = blockIdx.z >> 2, sp = blockIdx.z & 3;
    int klo = sp * 128, khi = klo + 128;
    size_t hoff = (size_t)b*NPTS*MEMD;
    gemm64(g_u + (size_t)b*NN, (const float*)0, (const float*)0, (const float*)0,
           1.f, NPTS, blockIdx.y*64, klo, khi,
           g_hp0 + hoff, g_hp1 + hoff, g_hp2 + hoff, g_hp3 + hoff,
           MEMD, blockIdx.x*64, MEMD,
           op_buf(sp), MEMD, b*NPTS + blockIdx.y*64, blockIdx.x*64, MEMD,
           (const float*)0, 1.f);
}

// ====== final combine (layer 1): out = (Σop) * (1/g_sum[2+b]) ======
__global__ void __launch_bounds__(256) k_comb(float* __restrict__ out)
{
    int t4 = blockIdx.x * 256 + threadIdx.x;     // 76800 float4s
    int row = t4 / 75;
    float inv = 1.f / g_sum[2 + (row >> 9)];
    float4 a = *(const float4*)&g_op0[(size_t)t4*4];
    float4 c = *(const float4*)&g_op1[(size_t)t4*4];
    float4 d = *(const float4*)&g_op2[(size_t)t4*4];
    float4 e = *(const float4*)&g_op3[(size_t)t4*4];
    float4 v = make_float4(((a.x+c.x)+(d.x+e.x))*inv, ((a.y+c.y)+(d.y+e.y))*inv,
                           ((a.z+c.z)+(d.z+e.z))*inv, ((a.w+c.w)+(d.w+e.w))*inv);
    *(float4*)&out[(size_t)t4*4] = v;
}

// ---------------- host ----------------
extern "C" void kernel_launch(void* const* d_in, const int* in_sizes, int n_in,
                              void* d_out, int out_size) {
    const float* feature = (const float*)d_in[0];
    const float* adj     = (const float*)d_in[1];
    const float* w0      = (const float*)d_in[2];
    const float* b0      = (const float*)d_in[3];
    const float* w1      = (const float*)d_in[4];
    const float* b1      = (const float*)d_in[5];
    const float* a1w     = (const float*)d_in[6];
    const float* a1b     = (const float*)d_in[7];
    const float* a2w     = (const float*)d_in[8];
    const float* a2b     = (const float*)d_in[9];
    float* out = (float*)d_out;

    dim3 gh(5, 16, 4);       // 320 CTAs x 256 thr
    dim3 gs(2, 16, 4);       // 128 CTAs
    dim3 ge(8, 8, BQ);       // 128 CTAs
    dim3 go(5, 8, 8);        // 320 CTAs (b x 4 splits)

    // ---- layer 0 ----
    k_h   <<<gh, 256>>>(feature, 0, w0, b0, INDIM, 0);
    k_s   <<<gs, 256>>>(a1w, a1b);
    k_e   <<<ge, 256>>>(adj, a2w, a2b, 0);
    k_out <<<go, 256>>>();

    // ---- layer 1 (k_h folds layer-0 out partials + 1/sum on the fly) ----
    k_h   <<<gh, 256>>>(nullptr, 1, w1, b1, MEMD, 1);
    k_s   <<<gs, 256>>>(a1w, a1b);
    k_e   <<<ge, 256>>>(adj, a2w, a2b, 1);
    k_out <<<go, 256>>>();
    k_comb<<<300, 256>>>(out);
}

// round 15
// speedup vs baseline: 2.5118x; 1.1788x over previous
#include <cuda_runtime.h>

#define BQ 2
#define NPTS 512
#define INDIM 512
#define MEMD 300
#define HIDD 64
#define NEG 0.01f
#define NN (NPTS*NPTS)

typedef unsigned long long ull;

// ---------------- scratch ----------------
__device__ float g_hp0[1024*MEMD], g_hp1[1024*MEMD], g_hp2[1024*MEMD], g_hp3[1024*MEMD];
__device__ float g_h [1024*MEMD];                      // combined h
__device__ float g_sp0[1024*128],  g_sp1[1024*128],  g_sp2[1024*128],  g_sp3[1024*128];
__device__ float g_op0[1024*MEMD], g_op1[1024*MEMD], g_op2[1024*MEMD], g_op3[1024*MEMD];
__device__ float g_f [1024*MEMD];                      // layer-0 output (combined+scaled)
__device__ float g_u [BQ*NN];
__device__ float g_sum[4];                             // [layer][batch]

// ---------------- f32x2 helpers ----------------
__device__ __forceinline__ ull dup2(float x) {
    ull r; asm("mov.b64 %0, {%1,%1};" : "=l"(r) : "f"(x)); return r;
}
__device__ __forceinline__ void ffma2(ull& d, ull a, ull b) {
    asm("fma.rn.f32x2 %0, %1, %2, %0;" : "+l"(d) : "l"(a), "l"(b));
}
__device__ __forceinline__ float2 unpk(ull v) {
    float2 r; asm("mov.b64 {%0,%1}, %2;" : "=f"(r.x), "=f"(r.y) : "l"(v)); return r;
}

// ---------------- cp.async helpers ----------------
__device__ __forceinline__ unsigned s2u(const void* p) {
    return (unsigned)__cvta_generic_to_shared(p);
}
__device__ __forceinline__ void cpa4(unsigned dst, const void* src, int sz) {
    asm volatile("cp.async.ca.shared.global [%0], [%1], 4, %2;"
                 :: "r"(dst), "l"(src), "r"(sz));
}
__device__ __forceinline__ void cpa16(unsigned dst, const void* src, int sz) {
    asm volatile("cp.async.ca.shared.global [%0], [%1], 16, %2;"
                 :: "r"(dst), "l"(src), "r"(sz));
}
__device__ __forceinline__ void cp_commit() {
    asm volatile("cp.async.commit_group;");
}
__device__ __forceinline__ void cp_wait1() {
    asm volatile("cp.async.wait_group 1;");
}

// ====== GEMM core: 64x64 tile, 256 thr, 4x4 micro, f32x2, cp.async 3-stage ======
// Single-source A and B.  C = cscale*acc + bias over k in [klo, khi).
__device__ __forceinline__ void gemm64cp(
    const float* __restrict__ A, int lda, int ar0, int klo, int khi,
    const float* __restrict__ B, int ldb, int bc0, int bcmax,
    float* __restrict__ C, int ldc, int cr0, int cc0, int ccmax,
    const float* __restrict__ bias, float cscale)
{
    __shared__ __align__(16) float As[3][16*68];   // [st][k][row], stride 68
    __shared__ __align__(16) float Bs[3][16*68];   // [st][k][col], stride 68
    int tid = threadIdx.x;
    int tx = tid & 15, ty = tid >> 4;              // tx: col-quad, ty: row-quad
    int ty4 = ty*4, tx4 = tx*4;
    int kA = tid & 15, rA = tid >> 4;              // A: 4 x 4B copies (rows rA+16p)
    int qB = tid & 15, kB = tid >> 4;              // B: 1 x 16B copy  (k kB, colquad qB)
    int bq = bc0 + qB*4;
    int bsz = (bcmax - bq) * 4;
    bsz = bsz < 0 ? 0 : (bsz > 16 ? 16 : bsz);     // partial 16B zero-filled at col tail
    int bqc = min(bq, bcmax - 4);
    ull acc[4][2] = {};
    int nch = (khi - klo + 15) >> 4;

    auto issue = [&](int c, int st) {
        int k0 = klo + c*16;
        int ka = k0 + kA;
        int asz = (ka < khi) ? 4 : 0;
        int kac = min(ka, khi - 1);
        #pragma unroll
        for (int p = 0; p < 4; p++)
            cpa4(s2u(&As[st][kA*68 + rA + 16*p]),
                 &A[(size_t)(ar0 + rA + 16*p)*lda + kac], asz);
        int kb = k0 + kB;
        int kbc = min(kb, khi - 1);
        cpa16(s2u(&Bs[st][kB*68 + qB*4]),
              &B[(size_t)kbc*ldb + bqc], (kb < khi) ? bsz : 0);
    };

    issue(0, 0); cp_commit();
    if (nch > 1) { issue(1, 1); } cp_commit();
    for (int c = 0; c < nch; c++) {
        cp_wait1();                                 // chunk c landed
        __syncthreads();                            // visible to all; buf (c-1)%3 free
        if (c + 2 < nch) { issue(c + 2, (c + 2) % 3); }
        cp_commit();                                // always commit (group bookkeeping)
        const float* as = As[c % 3];
        const float* bs = Bs[c % 3];
        #pragma unroll
        for (int k = 0; k < 16; k++) {
            float4 av = *(const float4*)&as[k*68 + ty4];
            ulonglong2 bv = *(const ulonglong2*)&bs[k*68 + tx4];
            ull a0 = dup2(av.x), a1 = dup2(av.y), a2 = dup2(av.z), a3 = dup2(av.w);
            ffma2(acc[0][0], a0, bv.x); ffma2(acc[0][1], a0, bv.y);
            ffma2(acc[1][0], a1, bv.x); ffma2(acc[1][1], a1, bv.y);
            ffma2(acc[2][0], a2, bv.x); ffma2(acc[2][1], a2, bv.y);
            ffma2(acc[3][0], a3, bv.x); ffma2(acc[3][1], a3, bv.y);
        }
    }
    int cc = cc0 + tx4;
    if (cc < ccmax) {
        float4 bb = bias ? *(const float4*)&bias[cc] : make_float4(0.f,0.f,0.f,0.f);
        #pragma unroll
        for (int r = 0; r < 4; r++) {
            float2 lo = unpk(acc[r][0]), hi = unpk(acc[r][1]);
            float4 v = make_float4(lo.x*cscale + bb.x, lo.y*cscale + bb.y,
                                   hi.x*cscale + bb.z, hi.y*cscale + bb.w);
            *(float4*)&C[(size_t)(cr0 + ty4 + r)*ldc + cc] = v;
        }
    }
}

__device__ float* hp_buf(int sp) {
    return sp == 0 ? g_hp0 : sp == 1 ? g_hp1 : sp == 2 ? g_hp2 : g_hp3;
}
__device__ float* sp_buf(int sp) {
    return sp == 0 ? g_sp0 : sp == 1 ? g_sp1 : sp == 2 ? g_sp2 : g_sp3;
}
__device__ float* op_buf(int sp) {
    return sp == 0 ? g_op0 : sp == 1 ? g_op1 : sp == 2 ? g_op2 : g_op3;
}

// ====== h partials = A @ W (+bias on sp0)  grid (5, 16, 4) = 320 CTAs ======
__global__ void __launch_bounds__(256) k_h(
    const float* __restrict__ Aext, int use_gf,
    const float* __restrict__ W, const float* __restrict__ bias,
    int Ktot, int lay)
{
    int sp = blockIdx.z;
    if (sp == 0 && blockIdx.x == 0 && blockIdx.y == 0 && threadIdx.x < 2)
        g_sum[lay*2 + threadIdx.x] = 0.f;
    int kq = (Ktot + 3) >> 2;
    int klo = sp * kq, khi = min(Ktot, klo + kq);
    const float* A = use_gf ? g_f : Aext;
    int lda = use_gf ? MEMD : Ktot;
    gemm64cp(A, lda, blockIdx.y*64, klo, khi,
             W, MEMD, blockIdx.x*64, MEMD,
             hp_buf(sp), MEMD, blockIdx.y*64, blockIdx.x*64, MEMD,
             sp == 0 ? bias : (const float*)0, 1.f);
}

// ====== comb_h: g_h = hp0+hp1+hp2+hp3  grid 300 x 256 ======
__global__ void __launch_bounds__(256) comb_h()
{
    int t4 = blockIdx.x * 256 + threadIdx.x;       // 76800 float4s
    float4 a = *(const float4*)&g_hp0[(size_t)t4*4];
    float4 b = *(const float4*)&g_hp1[(size_t)t4*4];
    float4 c = *(const float4*)&g_hp2[(size_t)t4*4];
    float4 d = *(const float4*)&g_hp3[(size_t)t4*4];
    float4 v = make_float4((a.x+b.x)+(c.x+d.x), (a.y+b.y)+(c.y+d.y),
                           (a.z+b.z)+(c.z+d.z), (a.w+b.w)+(c.w+d.w));
    *(float4*)&g_h[(size_t)t4*4] = v;
}

// ====== s partials = g_h @ a1w_half (+a1b on ct0/sp0)  grid (2, 16, 4) ======
__global__ void __launch_bounds__(256) k_s(
    const float* __restrict__ a1w, const float* __restrict__ a1b)
{
    int ct = blockIdx.x, sp = blockIdx.z;
    int kq = (MEMD + 3) >> 2;                      // 75
    int klo = sp * kq, khi = min(MEMD, klo + kq);
    gemm64cp(g_h, MEMD, blockIdx.y*64, klo, khi,
             a1w + (size_t)ct*MEMD*HIDD, HIDD, 0, HIDD,
             sp_buf(sp), 128, blockIdx.y*64, ct*64, 128,
             (ct == 0 && sp == 0) ? a1b : (const float*)0, 1.f);
}

// ====== u = exp(masked leaky(e)) + batch sum  (64x64, 256 thr)  grid (8,8,2) ======
__global__ void __launch_bounds__(256) k_e(
    const float* __restrict__ adj, const float* __restrict__ a2w,
    const float* __restrict__ a2b, int lay)
{
    __shared__ __align__(16) float Si[64][68];     // [h][i_local]
    __shared__ __align__(16) float Sj[64][68];     // [h][j_local]
    __shared__ float Wv[64];
    __shared__ float red[256];
    int tx = threadIdx.x & 15, ty = threadIdx.x >> 4;
    int tid = threadIdx.x;
    int b = blockIdx.z;
    int i0 = blockIdx.y * 64, j0 = blockIdx.x * 64;
    if (tid < 64) Wv[tid] = a2w[tid];
    #pragma unroll
    for (int p = 0; p < 16; p++) {
        int idx = tid + p*256;
        int h = idx & 63, r = idx >> 6;            // h-fast: coalesced
        size_t oi = (size_t)(b*NPTS + i0 + r)*128 + h;
        size_t oj = (size_t)(b*NPTS + j0 + r)*128 + 64 + h;
        Si[h][r] = (g_sp0[oi] + g_sp1[oi]) + (g_sp2[oi] + g_sp3[oi]);
        Sj[h][r] = (g_sp0[oj] + g_sp1[oj]) + (g_sp2[oj] + g_sp3[oj]);
    }
    __syncthreads();
    float acc[4][4] = {};
    int ty4 = ty*4, tx4 = tx*4;
    #pragma unroll 4
    for (int h = 0; h < 64; h++) {
        float w = Wv[h];
        float4 si = *(const float4*)&Si[h][ty4];
        float4 sj = *(const float4*)&Sj[h][tx4];
        float siv[4] = {si.x, si.y, si.z, si.w};
        float sjv[4] = {sj.x, sj.y, sj.z, sj.w};
        #pragma unroll
        for (int di = 0; di < 4; di++)
            #pragma unroll
            for (int dj = 0; dj < 4; dj++)
                acc[di][dj] = fmaf(fmaxf(siv[di] + sjv[dj], 0.f), w, acc[di][dj]);
    }
    float ab = a2b[0];
    float lsum = 0.f;
    #pragma unroll
    for (int di = 0; di < 4; di++) {
        int i = i0 + ty4 + di;
        float4 av = *(const float4*)&adj[(size_t)(b*NPTS + i)*NPTS + j0 + tx4];
        float am[4] = {av.x, av.y, av.z, av.w};
        float o[4];
        #pragma unroll
        for (int dj = 0; dj < 4; dj++) {
            float e = acc[di][dj] + ab;
            e = (e > 0.f) ? e : NEG * e;
            float lg = e * am[dj] + (1.f - am[dj]) * (-1e30f);
            o[dj] = __expf(lg);                    // masked -> exactly 0
        }
        *(float4*)&g_u[(size_t)b*NN + i*NPTS + j0 + tx4] =
            make_float4(o[0], o[1], o[2], o[3]);
        lsum += (o[0] + o[1]) + (o[2] + o[3]);
    }
    red[tid] = lsum;
    __syncthreads();
    for (int s = 128; s > 0; s >>= 1) {
        if (tid < s) red[tid] += red[tid + s];
        __syncthreads();
    }
    if (tid == 0) atomicAdd(&g_sum[lay*2 + b], red[0]);
}

// ====== out partials = U @ g_h[b]  grid (5, 8, 8: b*4+split) = 320 CTAs ======
__global__ void __launch_bounds__(256) k_out()
{
    int b = blockIdx.z >> 2, sp = blockIdx.z & 3;
    int klo = sp * 128, khi = klo + 128;
    gemm64cp(g_u + (size_t)b*NN, NPTS, blockIdx.y*64, klo, khi,
             g_h + (size_t)b*NPTS*MEMD, MEMD, blockIdx.x*64, MEMD,
             op_buf(sp), MEMD, b*NPTS + blockIdx.y*64, blockIdx.x*64, MEMD,
             (const float*)0, 1.f);
}

// ====== k_comb: dst = (Σop) * (1/g_sum[lay*2+b]);  dst = g_f (lay0) or out ======
__global__ void __launch_bounds__(256) k_comb(float* __restrict__ out_ext,
                                              int to_gf, int lay)
{
    float* dst = to_gf ? g_f : out_ext;
    int t4 = blockIdx.x * 256 + threadIdx.x;       // 76800 float4s (75 per row)
    int row = t4 / 75;
    float inv = 1.f / g_sum[lay*2 + (row >> 9)];
    float4 a = *(const float4*)&g_op0[(size_t)t4*4];
    float4 b = *(const float4*)&g_op1[(size_t)t4*4];
    float4 c = *(const float4*)&g_op2[(size_t)t4*4];
    float4 d = *(const float4*)&g_op3[(size_t)t4*4];
    float4 v = make_float4(((a.x+b.x)+(c.x+d.x))*inv, ((a.y+b.y)+(c.y+d.y))*inv,
                           ((a.z+b.z)+(c.z+d.z))*inv, ((a.w+b.w)+(c.w+d.w))*inv);
    *(float4*)&dst[(size_t)t4*4] = v;
}

// ---------------- host ----------------
extern "C" void kernel_launch(void* const* d_in, const int* in_sizes, int n_in,
                              void* d_out, int out_size) {
    const float* feature = (const float*)d_in[0];
    const float* adj     = (const float*)d_in[1];
    const float* w0      = (const float*)d_in[2];
    const float* b0      = (const float*)d_in[3];
    const float* w1      = (const float*)d_in[4];
    const float* b1      = (const float*)d_in[5];
    const float* a1w     = (const float*)d_in[6];
    const float* a1b     = (const float*)d_in[7];
    const float* a2w     = (const float*)d_in[8];
    const float* a2b     = (const float*)d_in[9];
    float* out = (float*)d_out;

    dim3 gh(5, 16, 4);       // 320 CTAs x 256 thr
    dim3 gs(2, 16, 4);       // 128 CTAs
    dim3 ge(8, 8, BQ);       // 128 CTAs
    dim3 go(5, 8, 8);        // 320 CTAs

    // ---- layer 0 ----
    k_h   <<<gh, 256>>>(feature, 0, w0, b0, INDIM, 0);
    comb_h<<<300, 256>>>();
    k_s   <<<gs, 256>>>(a1w, a1b);
    k_e   <<<ge, 256>>>(adj, a2w, a2b, 0);
    k_out <<<go, 256>>>();
    k_comb<<<300, 256>>>(out, 1, 0);               // -> g_f

    // ---- layer 1 ----
    k_h   <<<gh, 256>>>(nullptr, 1, w1, b1, MEMD, 1);
    comb_h<<<300, 256>>>();
    k_s   <<<gs, 256>>>(a1w, a1b);
    k_e   <<<ge, 256>>>(adj, a2w, a2b, 1);
    k_out <<<go, 256>>>();
    k_comb<<<300, 256>>>(out, 0, 1);               // -> d_out
}